// round 2
// baseline (speedup 1.0000x reference)
#include <cuda_runtime.h>
#include <math.h>

#define BB 16
#define SS 8192
#define HH 512
#define NROWS (BB*SS)

#define BM 128
#define BN 128
#define BK 16
#define PAD 4   // smem row padding (keeps 16B alignment: (128+4)*4 = 528 bytes)

// Scratch (device globals — no allocation allowed)
__device__ float g_qproj[BB*HH];
__device__ float g_scores[BB*SS];
__device__ float g_ctx_part[BB*8*HH];

// ---------------------------------------------------------------------------
// q_proj[b][o] = query[b,:] . W_q[o,:]
// ---------------------------------------------------------------------------
__global__ void qproj_kernel(const float* __restrict__ query,
                             const float* __restrict__ Wq) {
    int b = blockIdx.x;
    int o = threadIdx.x;          // 512 threads
    __shared__ float q[HH];
    q[o] = query[b*HH + o];
    __syncthreads();
    const float* w = Wq + (size_t)o*HH;
    float acc = 0.f;
#pragma unroll 8
    for (int k = 0; k < HH; k++) acc += q[k] * w[k];
    g_qproj[b*HH + o] = acc;
}

// ---------------------------------------------------------------------------
// scores[m] = sum_o v[o] * tanh( enc[m,:].W_h[o,:] + qproj[b][o] )
// Fused tiled SGEMM (128x128 tile, 8x8/thread, K-slab 16) + epilogue reduce.
// ---------------------------------------------------------------------------
__global__ __launch_bounds__(256, 2)
void scores_kernel(const float* __restrict__ enc,
                   const float* __restrict__ Wh,
                   const float* __restrict__ v) {
    __shared__ float As[BK][BM + PAD];
    __shared__ float Bs[BK][BN + PAD];
    __shared__ float qs[BN];
    __shared__ float vs[BN];
    __shared__ float scoreAcc[BM];

    const int tid = threadIdx.x;            // 256 threads
    const int tx = tid & 15;                // 16 col groups (8 cols each)
    const int ty = tid >> 4;                // 16 row groups (8 rows each)
    const int m0 = blockIdx.x * BM;         // global row (flattened b*S+s)
    const int b  = m0 / SS;                 // S % BM == 0 -> tile in one batch
    const float* qp = g_qproj + b*HH;

    if (tid < BM) scoreAcc[tid] = 0.f;

    for (int nc = 0; nc < HH/BN; nc++) {
        const int n0 = nc * BN;
        if (tid < BN) { qs[tid] = qp[n0 + tid]; vs[tid] = v[n0 + tid]; }

        float acc[8][8];
#pragma unroll
        for (int i = 0; i < 8; i++)
#pragma unroll
            for (int j = 0; j < 8; j++) acc[i][j] = 0.f;

        for (int k0 = 0; k0 < HH; k0 += BK) {
            __syncthreads();
            // load A slab (enc rows m0..m0+127, cols k0..k0+15) -> As[k][m]
            {
                int f = tid;
#pragma unroll
                for (int r = 0; r < 2; r++, f += 256) {
                    int row = f >> 2;
                    int kq  = (f & 3) << 2;
                    float4 val = *(const float4*)(enc + (size_t)(m0 + row)*HH + k0 + kq);
                    As[kq+0][row] = val.x; As[kq+1][row] = val.y;
                    As[kq+2][row] = val.z; As[kq+3][row] = val.w;
                }
            }
            // load B slab (W_h rows n0..n0+127, cols k0..k0+15) -> Bs[k][n]
            {
                int f = tid;
#pragma unroll
                for (int r = 0; r < 2; r++, f += 256) {
                    int row = f >> 2;
                    int kq  = (f & 3) << 2;
                    float4 val = *(const float4*)(Wh + (size_t)(n0 + row)*HH + k0 + kq);
                    Bs[kq+0][row] = val.x; Bs[kq+1][row] = val.y;
                    Bs[kq+2][row] = val.z; Bs[kq+3][row] = val.w;
                }
            }
            __syncthreads();
#pragma unroll
            for (int k = 0; k < BK; k++) {
                float a[8], bb[8];
                *(float4*)(a)     = *(const float4*)&As[k][ty*8];
                *(float4*)(a + 4) = *(const float4*)&As[k][ty*8 + 4];
                *(float4*)(bb)     = *(const float4*)&Bs[k][tx*8];
                *(float4*)(bb + 4) = *(const float4*)&Bs[k][tx*8 + 4];
#pragma unroll
                for (int i = 0; i < 8; i++)
#pragma unroll
                    for (int j = 0; j < 8; j++)
                        acc[i][j] += a[i] * bb[j];
            }
        }

        // epilogue: partial score per row = sum_j tanh(acc+q)*v
        float part[8];
#pragma unroll
        for (int i = 0; i < 8; i++) part[i] = 0.f;
#pragma unroll
        for (int j = 0; j < 8; j++) {
            float qv = qs[tx*8 + j];
            float vv = vs[tx*8 + j];
#pragma unroll
            for (int i = 0; i < 8; i++)
                part[i] += tanhf(acc[i][j] + qv) * vv;
        }
        // reduce over the 16 tx lanes (xor 8..1 stays within 16-lane halves)
#pragma unroll
        for (int i = 0; i < 8; i++) {
#pragma unroll
            for (int off = 8; off; off >>= 1)
                part[i] += __shfl_xor_sync(0xffffffffu, part[i], off);
        }
        if (tx == 0) {
#pragma unroll
            for (int i = 0; i < 8; i++)
                scoreAcc[ty*8 + i] += part[i];
        }
        __syncthreads();   // protect qs/vs/scoreAcc before next chunk
    }
    if (tid < BM) g_scores[m0 + tid] = scoreAcc[tid];
}

// ---------------------------------------------------------------------------
// softmax over S per batch; writes alpha directly into d_out region
// ---------------------------------------------------------------------------
__global__ void softmax_kernel(float* __restrict__ alpha) {
    const int b = blockIdx.x;
    const int tid = threadIdx.x;    // 1024 threads
    const float* sc = g_scores + b*SS;
    __shared__ float red[32];

    float m = -1e30f;
    for (int s = tid; s < SS; s += 1024) m = fmaxf(m, sc[s]);
#pragma unroll
    for (int off = 16; off; off >>= 1)
        m = fmaxf(m, __shfl_xor_sync(0xffffffffu, m, off));
    if ((tid & 31) == 0) red[tid >> 5] = m;
    __syncthreads();
    if (tid < 32) {
        float x = red[tid];
#pragma unroll
        for (int off = 16; off; off >>= 1)
            x = fmaxf(x, __shfl_xor_sync(0xffffffffu, x, off));
        if (tid == 0) red[0] = x;
    }
    __syncthreads();
    m = red[0];
    __syncthreads();

    float sum = 0.f;
    for (int s = tid; s < SS; s += 1024) sum += expf(sc[s] - m);
#pragma unroll
    for (int off = 16; off; off >>= 1)
        sum += __shfl_xor_sync(0xffffffffu, sum, off);
    if ((tid & 31) == 0) red[tid >> 5] = sum;
    __syncthreads();
    if (tid < 32) {
        float x = red[tid];
#pragma unroll
        for (int off = 16; off; off >>= 1)
            x += __shfl_xor_sync(0xffffffffu, x, off);
        if (tid == 0) red[0] = x;
    }
    __syncthreads();
    const float inv = 1.f / red[0];

    for (int s = tid; s < SS; s += 1024)
        alpha[b*SS + s] = expf(sc[s] - m) * inv;
}

// ---------------------------------------------------------------------------
// context partials: block (b, sc) handles 1024 s-rows x all 512 h
// ---------------------------------------------------------------------------
__global__ void ctx_part_kernel(const float* __restrict__ enc,
                                const float* __restrict__ alpha) {
    const int b = blockIdx.x, sc = blockIdx.y;
    const int t = threadIdx.x;   // 128 threads, 4 h each (float4)
    __shared__ float al[1024];
    for (int i = t; i < 1024; i += 128)
        al[i] = alpha[b*SS + sc*1024 + i];
    __syncthreads();

    const float4* e = (const float4*)(enc + (size_t)b*SS*HH + (size_t)sc*1024*HH) + t;
    float4 acc = make_float4(0.f, 0.f, 0.f, 0.f);
#pragma unroll 4
    for (int s = 0; s < 1024; s++) {
        float a = al[s];
        float4 vv = e[(size_t)s*128];
        acc.x += a * vv.x; acc.y += a * vv.y;
        acc.z += a * vv.z; acc.w += a * vv.w;
    }
    ((float4*)(g_ctx_part + (size_t)(b*8 + sc)*HH))[t] = acc;
}

__global__ void ctx_reduce_kernel(float* __restrict__ ctx) {
    const int b = blockIdx.x, h = threadIdx.x;   // 512 threads
    float s = 0.f;
#pragma unroll
    for (int i = 0; i < 8; i++)
        s += g_ctx_part[(size_t)(b*8 + i)*HH + h];
    ctx[b*HH + h] = s;
}

// ---------------------------------------------------------------------------
extern "C" void kernel_launch(void* const* d_in, const int* in_sizes, int n_in,
                              void* d_out, int out_size) {
    const float* enc   = (const float*)d_in[0];   // (B,S,H)
    const float* query = (const float*)d_in[1];   // (B,H)
    const float* Wh    = (const float*)d_in[2];   // (H,H)
    const float* Wq    = (const float*)d_in[3];   // (H,H)
    const float* v     = (const float*)d_in[4];   // (H,)

    float* ctx   = (float*)d_out;            // context: B*H floats
    float* alpha = (float*)d_out + BB*HH;    // alpha:   B*S floats

    qproj_kernel<<<BB, HH>>>(query, Wq);
    scores_kernel<<<NROWS/BM, 256>>>(enc, Wh, v);
    softmax_kernel<<<BB, 1024>>>(alpha);
    ctx_part_kernel<<<dim3(BB, 8), 128>>>(enc, alpha);
    ctx_reduce_kernel<<<BB, HH>>>(ctx);
}

// round 4
// speedup vs baseline: 1.6342x; 1.6342x over previous
#include <cuda_runtime.h>
#include <cuda_bf16.h>
#include <math.h>
#include <stdint.h>

#define BB 16
#define SS 8192
#define HH 512
#define NROWS (BB*SS)

// ---------------------------------------------------------------------------
// helpers
// ---------------------------------------------------------------------------
__device__ __forceinline__ uint32_t smem_u32(const void* p) {
    uint32_t a;
    asm("{ .reg .u64 t; cvta.to.shared.u64 t, %1; cvt.u32.u64 %0, t; }" : "=r"(a) : "l"(p));
    return a;
}
#define SW128(o) ((o) ^ (((o) >> 3) & 0x70))

#define LDSM4(r0,r1,r2,r3,addr)                                               \
    asm volatile("ldmatrix.sync.aligned.m8n8.x4.shared.b16 {%0,%1,%2,%3}, [%4];" \
        : "=r"(r0),"=r"(r1),"=r"(r2),"=r"(r3) : "r"(addr))

__device__ __forceinline__ void mma16816(float* c, const uint32_t* a,
                                         uint32_t b0, uint32_t b1) {
    asm volatile(
        "mma.sync.aligned.m16n8k16.row.col.f32.bf16.bf16.f32 "
        "{%0,%1,%2,%3}, {%4,%5,%6,%7}, {%8,%9}, {%0,%1,%2,%3};"
        : "+f"(c[0]), "+f"(c[1]), "+f"(c[2]), "+f"(c[3])
        : "r"(a[0]), "r"(a[1]), "r"(a[2]), "r"(a[3]), "r"(b0), "r"(b1));
}

__device__ __forceinline__ float fast_tanh(float x) {
    float xc = fminf(x, 30.f);                 // tanh(30)==1 in fp32; avoid inf/inf
    float e  = __expf(2.f * xc);
    return __fdividef(e - 1.f, e + 1.f);
}

// ---------------------------------------------------------------------------
// scratch
// ---------------------------------------------------------------------------
__device__ float g_qproj[BB*HH];
__device__ float g_scores[BB*SS];
__device__ float g_ctx_part[BB*64*HH];
__device__ __align__(16) __nv_bfloat16 g_WhSplit[2*HH*HH];   // [comp][o][k]

// smem layout (bytes) for scores kernel
#define SM_A     0                     // 2 comps x 128 rows x 128B = 32KB
#define SM_B     32768                 // 2 comps x 128 rows x 128B = 32KB
#define SM_Q     65536                 // 128 floats
#define SM_V     66048                 // 128 floats
#define SM_PART  66560                 // 4 x 128 floats
#define SM_TOTAL 68608

// ---------------------------------------------------------------------------
// split W_h into hi/mid bf16 components
// ---------------------------------------------------------------------------
__global__ void whsplit_kernel(const float* __restrict__ Wh) {
    int i0 = (blockIdx.x * 256 + threadIdx.x) * 4;
#pragma unroll
    for (int j = 0; j < 4; j++) {
        int i = i0 + j;
        float x = Wh[i];
        __nv_bfloat16 h = __float2bfloat16(x);
        __nv_bfloat16 m = __float2bfloat16(x - __bfloat162float(h));
        g_WhSplit[i] = h;
        g_WhSplit[HH*HH + i] = m;
    }
}

// ---------------------------------------------------------------------------
// q_proj[b][o] = query[b,:] . W_q[o,:]   (fp32, exact)
// ---------------------------------------------------------------------------
__global__ void qproj_kernel(const float* __restrict__ query,
                             const float* __restrict__ Wq) {
    int b = blockIdx.x, o = threadIdx.x;
    __shared__ float q[HH];
    q[o] = query[b*HH + o];
    __syncthreads();
    const float* w = Wq + (size_t)o*HH;
    float acc = 0.f;
#pragma unroll 8
    for (int k = 0; k < HH; k++) acc += q[k] * w[k];
    g_qproj[b*HH + o] = acc;
}

// ---------------------------------------------------------------------------
// scores via warp-level bf16 mma (3-product emulated fp32)
// CTA: 128 rows x full H. 8 warps = 2(m) x 4(n), warp tile 64x32.
// nc: 4 chunks of 128 output channels; kc: 8 chunks of 64 k.
// ---------------------------------------------------------------------------
__global__ __launch_bounds__(256, 2)
void scores_mma_kernel(const float* __restrict__ enc,
                       const float* __restrict__ v) {
    extern __shared__ char smem[];
    const uint32_t sb = smem_u32(smem);
    const int tid  = threadIdx.x;
    const int lane = tid & 31;
    const int wid  = tid >> 5;
    const int wm   = wid & 1;          // 0..1  (64 rows each)
    const int wn   = wid >> 1;         // 0..3  (32 cols each)
    const int m0   = blockIdx.x * 128;
    const int b    = m0 / SS;

    float* qs   = (float*)(smem + SM_Q);
    float* vs   = (float*)(smem + SM_V);
    float* part = (float*)(smem + SM_PART);   // [4][128]

    // per-thread ldmatrix base offsets
    const uint32_t aRow = (uint32_t)(wm*64 + (lane & 15)) * 128u;
    const uint32_t aCol = ((lane >> 4) & 1) * 16u;
    const uint32_t bRow = (uint32_t)(wn*32 + (lane & 7) + ((lane & 16) ? 8 : 0)) * 128u;
    const uint32_t bCol = ((lane & 8) ? 16u : 0u);

    float rowsc[8];
#pragma unroll
    for (int i = 0; i < 8; i++) rowsc[i] = 0.f;

    const uint4* wsrc = (const uint4*)g_WhSplit;

    for (int nc = 0; nc < 4; nc++) {
        if (tid < 128) {
            qs[tid] = g_qproj[b*HH + nc*128 + tid];
            vs[tid] = v[nc*128 + tid];
        }

        float c[4][4][4];
#pragma unroll
        for (int mf = 0; mf < 4; mf++)
#pragma unroll
            for (int nf = 0; nf < 4; nf++)
#pragma unroll
                for (int e = 0; e < 4; e++) c[mf][nf][e] = 0.f;

        for (int kc = 0; kc < 8; kc++) {
            __syncthreads();   // smem A/B safe to overwrite
            // ---- A: 128 rows x 64 fp32 -> hi/mid bf16, swizzled
#pragma unroll
            for (int i = 0; i < 8; i++) {
                int f = tid + i*256;           // 0..2047
                int m = f >> 4, jq = f & 15;
                float4 x = *(const float4*)(enc + (size_t)(m0+m)*HH + kc*64 + jq*4);
                __nv_bfloat162 h01 = __float22bfloat162_rn(make_float2(x.x, x.y));
                __nv_bfloat162 h23 = __float22bfloat162_rn(make_float2(x.z, x.w));
                float2 f01 = __bfloat1622float2(h01);
                float2 f23 = __bfloat1622float2(h23);
                __nv_bfloat162 m01 = __float22bfloat162_rn(make_float2(x.x - f01.x, x.y - f01.y));
                __nv_bfloat162 m23 = __float22bfloat162_rn(make_float2(x.z - f23.x, x.w - f23.y));
                uint32_t off = SW128((uint32_t)(m*128 + jq*8));
                *(uint2*)(smem + SM_A + off) =
                    make_uint2(*(uint32_t*)&h01, *(uint32_t*)&h23);
                *(uint2*)(smem + SM_A + 16384 + off) =
                    make_uint2(*(uint32_t*)&m01, *(uint32_t*)&m23);
            }
            // ---- B: 2 comps x 128 rows x 128B from pre-split W_h
#pragma unroll
            for (int i = 0; i < 8; i++) {
                int f = tid + i*256;           // 0..2047
                int comp = f >> 10;
                int rem = f & 1023;
                int n = rem >> 3, j = rem & 7;
                uint4 w = wsrc[comp*32768 + (nc*128 + n)*64 + kc*8 + j];
                uint32_t off = SW128((uint32_t)(n*128 + j*16));
                *(uint4*)(smem + SM_B + comp*16384 + off) = w;
            }
            __syncthreads();

            // ---- 3 products: (Ah,Bh), (Ah,Bm), (Am,Bh)
#pragma unroll
            for (int p = 0; p < 3; p++) {
                const uint32_t ca = (p == 2) ? 16384u : 0u;
                const uint32_t cb = (p == 1) ? 16384u : 0u;
#pragma unroll
                for (int ks = 0; ks < 4; ks++) {
                    uint32_t a[4][4];
#pragma unroll
                    for (int mf = 0; mf < 4; mf++) {
                        uint32_t ad = sb + SM_A + ca +
                            SW128(aRow + (uint32_t)mf*2048u + (uint32_t)ks*32u + aCol);
                        LDSM4(a[mf][0], a[mf][1], a[mf][2], a[mf][3], ad);
                    }
                    uint32_t bfr[4][2];
#pragma unroll
                    for (int n2 = 0; n2 < 2; n2++) {
                        uint32_t bd = sb + SM_B + cb +
                            SW128(bRow + (uint32_t)n2*2048u + (uint32_t)ks*32u + bCol);
                        uint32_t r0, r1, r2, r3;
                        LDSM4(r0, r1, r2, r3, bd);
                        bfr[n2*2][0] = r0;   bfr[n2*2][1] = r1;
                        bfr[n2*2+1][0] = r2; bfr[n2*2+1][1] = r3;
                    }
#pragma unroll
                    for (int mf = 0; mf < 4; mf++)
#pragma unroll
                        for (int nf = 0; nf < 4; nf++)
                            mma16816(c[mf][nf], a[mf], bfr[nf][0], bfr[nf][1]);
                }
            }
        }

        // ---- epilogue for this 128-channel chunk: tanh(d+q)*v, sum over cols
        __syncthreads();   // qs/vs visible, mma done
#pragma unroll
        for (int mf = 0; mf < 4; mf++)
#pragma unroll
            for (int nf = 0; nf < 4; nf++) {
                int nb = wn*32 + nf*8 + (lane & 3)*2;
                float q0 = qs[nb],   v0 = vs[nb];
                float q1 = qs[nb+1], v1 = vs[nb+1];
                rowsc[mf*2]   += fast_tanh(c[mf][nf][0] + q0)*v0
                               + fast_tanh(c[mf][nf][1] + q1)*v1;
                rowsc[mf*2+1] += fast_tanh(c[mf][nf][2] + q0)*v0
                               + fast_tanh(c[mf][nf][3] + q1)*v1;
            }
        __syncthreads();   // before qs/vs overwritten next nc
    }

    // reduce over the 4 lanes sharing each row
#pragma unroll
    for (int i = 0; i < 8; i++) {
        rowsc[i] += __shfl_xor_sync(~0u, rowsc[i], 1);
        rowsc[i] += __shfl_xor_sync(~0u, rowsc[i], 2);
    }
    if ((lane & 3) == 0) {
        int r = lane >> 2;
#pragma unroll
        for (int mf = 0; mf < 4; mf++) {
            part[wn*128 + wm*64 + mf*16 + r]     = rowsc[mf*2];
            part[wn*128 + wm*64 + mf*16 + r + 8] = rowsc[mf*2+1];
        }
    }
    __syncthreads();
    if (tid < 128)
        g_scores[m0 + tid] = part[tid] + part[128+tid] + part[256+tid] + part[384+tid];
}

// ---------------------------------------------------------------------------
// softmax over S per batch
// ---------------------------------------------------------------------------
__global__ void softmax_kernel(float* __restrict__ alpha) {
    const int b = blockIdx.x;
    const int tid = threadIdx.x;    // 1024
    const float* sc = g_scores + b*SS;
    __shared__ float red[32];

    float m = -1e30f;
    for (int s = tid; s < SS; s += 1024) m = fmaxf(m, sc[s]);
#pragma unroll
    for (int off = 16; off; off >>= 1) m = fmaxf(m, __shfl_xor_sync(~0u, m, off));
    if ((tid & 31) == 0) red[tid >> 5] = m;
    __syncthreads();
    if (tid < 32) {
        float x = red[tid];
#pragma unroll
        for (int off = 16; off; off >>= 1) x = fmaxf(x, __shfl_xor_sync(~0u, x, off));
        if (tid == 0) red[0] = x;
    }
    __syncthreads();
    m = red[0];
    __syncthreads();

    float sum = 0.f;
    for (int s = tid; s < SS; s += 1024) sum += expf(sc[s] - m);
#pragma unroll
    for (int off = 16; off; off >>= 1) sum += __shfl_xor_sync(~0u, sum, off);
    if ((tid & 31) == 0) red[tid >> 5] = sum;
    __syncthreads();
    if (tid < 32) {
        float x = red[tid];
#pragma unroll
        for (int off = 16; off; off >>= 1) x += __shfl_xor_sync(~0u, x, off);
        if (tid == 0) red[0] = x;
    }
    __syncthreads();
    const float inv = 1.f / red[0];
    for (int s = tid; s < SS; s += 1024)
        alpha[b*SS + s] = expf(sc[s] - m) * inv;
}

// ---------------------------------------------------------------------------
// context: partials over 64 s-chunks of 128 rows, then reduce
// ---------------------------------------------------------------------------
__global__ void ctx_part_kernel(const float* __restrict__ enc,
                                const float* __restrict__ alpha) {
    const int b = blockIdx.x, sc = blockIdx.y;   // 16 x 64
    const int t = threadIdx.x;                    // 128
    __shared__ float al[128];
    al[t] = alpha[b*SS + sc*128 + t];
    __syncthreads();

    const float4* e = (const float4*)(enc + (size_t)b*SS*HH + (size_t)sc*128*HH) + t;
    float4 acc = make_float4(0.f, 0.f, 0.f, 0.f);
#pragma unroll 4
    for (int s = 0; s < 128; s++) {
        float a = al[s];
        float4 vv = e[(size_t)s*128];
        acc.x += a*vv.x; acc.y += a*vv.y; acc.z += a*vv.z; acc.w += a*vv.w;
    }
    ((float4*)(g_ctx_part + (size_t)(b*64 + sc)*HH))[t] = acc;
}

__global__ void ctx_reduce_kernel(float* __restrict__ ctx) {
    const int b = blockIdx.x, h = threadIdx.x;
    float s = 0.f;
#pragma unroll
    for (int i = 0; i < 64; i++)
        s += g_ctx_part[(size_t)(b*64 + i)*HH + h];
    ctx[b*HH + h] = s;
}

// ---------------------------------------------------------------------------
extern "C" void kernel_launch(void* const* d_in, const int* in_sizes, int n_in,
                              void* d_out, int out_size) {
    const float* enc   = (const float*)d_in[0];
    const float* query = (const float*)d_in[1];
    const float* Wh    = (const float*)d_in[2];
    const float* Wq    = (const float*)d_in[3];
    const float* v     = (const float*)d_in[4];

    float* ctx   = (float*)d_out;
    float* alpha = (float*)d_out + BB*HH;

    cudaFuncSetAttribute(scores_mma_kernel,
                         cudaFuncAttributeMaxDynamicSharedMemorySize, SM_TOTAL);

    whsplit_kernel<<<HH*HH/1024, 256>>>(Wh);
    qproj_kernel<<<BB, HH>>>(query, Wq);
    scores_mma_kernel<<<NROWS/128, 256, SM_TOTAL>>>(enc, v);
    softmax_kernel<<<BB, 1024>>>(alpha);
    ctx_part_kernel<<<dim3(BB, 64), 128>>>(enc, alpha);
    ctx_reduce_kernel<<<BB, HH>>>(ctx);
}

// round 5
// speedup vs baseline: 1.9824x; 1.2131x over previous
#include <cuda_runtime.h>
#include <cuda_fp16.h>
#include <math.h>
#include <stdint.h>

#define BB 16
#define SS 8192
#define HH 512
#define NROWS (BB*SS)

// ---------------------------------------------------------------------------
// helpers
// ---------------------------------------------------------------------------
__device__ __forceinline__ uint32_t smem_u32(const void* p) {
    uint32_t a;
    asm("{ .reg .u64 t; cvta.to.shared.u64 t, %1; cvt.u32.u64 %0, t; }" : "=r"(a) : "l"(p));
    return a;
}
#define SW128(o) ((o) ^ (((o) >> 3) & 0x70))

#define LDSM4(r0,r1,r2,r3,addr)                                               \
    asm volatile("ldmatrix.sync.aligned.m8n8.x4.shared.b16 {%0,%1,%2,%3}, [%4];" \
        : "=r"(r0),"=r"(r1),"=r"(r2),"=r"(r3) : "r"(addr))

#define CP_ASYNC16(dst, src)                                                  \
    asm volatile("cp.async.ca.shared.global [%0], [%1], 16;" :: "r"(dst), "l"(src) : "memory")
#define CP_COMMIT()  asm volatile("cp.async.commit_group;" ::: "memory")
#define CP_WAIT0()   asm volatile("cp.async.wait_group 0;" ::: "memory")

__device__ __forceinline__ void mma16816(float* c, const uint32_t* a,
                                         uint32_t b0, uint32_t b1) {
    asm volatile(
        "mma.sync.aligned.m16n8k16.row.col.f32.f16.f16.f32 "
        "{%0,%1,%2,%3}, {%4,%5,%6,%7}, {%8,%9}, {%0,%1,%2,%3};"
        : "+f"(c[0]), "+f"(c[1]), "+f"(c[2]), "+f"(c[3])
        : "r"(a[0]), "r"(a[1]), "r"(a[2]), "r"(a[3]), "r"(b0), "r"(b1));
}

__device__ __forceinline__ float fast_tanh(float x) {
    float xc = fminf(x, 30.f);
    float e  = __expf(2.f * xc);
    return __fdividef(e - 1.f, e + 1.f);
}

// ---------------------------------------------------------------------------
// scratch
// ---------------------------------------------------------------------------
__device__ float g_qproj[BB*HH];
__device__ float g_scores[BB*SS];
__device__ float g_ctx_part[BB*64*HH];
__device__ __align__(16) __half g_WhSplit[2*HH*HH];   // [comp][o][k], fp16 hi/lo

// smem layout (bytes): 2-stage double buffer
#define SM_A     0                      // 2 stages x 128 rows x 128B = 32KB
#define SM_B     32768                  // 2 stages x 2 comps x 128 rows x 128B = 64KB
#define SM_Q     98304                  // 128 floats
#define SM_V     98816                  // 128 floats
#define SM_PART  99328                  // 4 x 128 floats
#define SM_TOTAL 101376

// ---------------------------------------------------------------------------
// split W_h into hi/lo fp16 components
// ---------------------------------------------------------------------------
__global__ void whsplit_kernel(const float* __restrict__ Wh) {
    int i0 = (blockIdx.x * 256 + threadIdx.x) * 4;
#pragma unroll
    for (int j = 0; j < 4; j++) {
        int i = i0 + j;
        float x = Wh[i];
        __half h = __float2half_rn(x);
        __half l = __float2half_rn(x - __half2float(h));
        g_WhSplit[i] = h;
        g_WhSplit[HH*HH + i] = l;
    }
}

// ---------------------------------------------------------------------------
// q_proj[b][o] = query[b,:] . W_q[o,:]   (fp32, exact)
// ---------------------------------------------------------------------------
__global__ void qproj_kernel(const float* __restrict__ query,
                             const float* __restrict__ Wq) {
    int b = blockIdx.x, o = threadIdx.x;
    __shared__ float q[HH];
    q[o] = query[b*HH + o];
    __syncthreads();
    const float* w = Wq + (size_t)o*HH;
    float acc = 0.f;
#pragma unroll 8
    for (int k = 0; k < HH; k++) acc += q[k] * w[k];
    g_qproj[b*HH + o] = acc;
}

// ---------------------------------------------------------------------------
// scores via fp16 mma, 2-product emulated fp32:
//   D = Ah*Bh + Ah*Bl  (A = enc -> fp16, B = W_h pre-split hi/lo)
// CTA: 128 rows x full H. 8 warps = 2(m) x 4(n), warp tile 64x32.
// nc: 4 chunks of 128 output channels; kc: 8 chunks of 64 k, double-buffered.
// ---------------------------------------------------------------------------
__global__ __launch_bounds__(256, 2)
void scores_mma_kernel(const float* __restrict__ enc,
                       const float* __restrict__ v) {
    extern __shared__ char smem[];
    const uint32_t sb = smem_u32(smem);
    const int tid  = threadIdx.x;
    const int lane = tid & 31;
    const int wid  = tid >> 5;
    const int wm   = wid & 1;          // 0..1  (64 rows each)
    const int wn   = wid >> 1;         // 0..3  (32 cols each)
    const int m0   = blockIdx.x * 128;
    const int b    = m0 / SS;

    float* qs   = (float*)(smem + SM_Q);
    float* vs   = (float*)(smem + SM_V);
    float* part = (float*)(smem + SM_PART);   // [4][128]

    // per-thread ldmatrix base offsets (within a 128-row x 128B tile)
    const uint32_t aRow = (uint32_t)(wm*64 + (lane & 15)) * 128u;
    const uint32_t aCol = ((lane >> 4) & 1) * 16u;
    const uint32_t bRow = (uint32_t)(wn*32 + (lane & 7) + ((lane & 16) ? 8 : 0)) * 128u;
    const uint32_t bCol = ((lane & 8) ? 16u : 0u);

    // A-loader / B-loader index precompute
    const int am  = tid >> 4;            // row group for A stores (m = am + 16i? no: f>>4)
    const uint4* wsrc = (const uint4*)g_WhSplit;   // 64 uint4 per o-row

    float rowsc[8];
#pragma unroll
    for (int i = 0; i < 8; i++) rowsc[i] = 0.f;
    (void)am;

    for (int nc = 0; nc < 4; nc++) {
        if (tid < 128) {
            qs[tid] = g_qproj[b*HH + nc*128 + tid];
            vs[tid] = v[nc*128 + tid];
        }

        float c[4][4][4];
#pragma unroll
        for (int mf = 0; mf < 4; mf++)
#pragma unroll
            for (int nf = 0; nf < 4; nf++)
#pragma unroll
                for (int e = 0; e < 4; e++) c[mf][nf][e] = 0.f;

        // ---- prologue: load kc=0 into stage 0
        {
#pragma unroll
            for (int i = 0; i < 8; i++) {               // A: 128x64 fp32 -> fp16
                int f = tid + i*256;
                int m = f >> 4, jq = f & 15;
                float4 x = *(const float4*)(enc + (size_t)(m0+m)*HH + jq*4);
                __half2 h01 = __float22half2_rn(make_float2(x.x, x.y));
                __half2 h23 = __float22half2_rn(make_float2(x.z, x.w));
                uint32_t off = SW128((uint32_t)(m*128 + jq*8));
                *(uint2*)(smem + SM_A + off) =
                    make_uint2(*(uint32_t*)&h01, *(uint32_t*)&h23);
            }
#pragma unroll
            for (int i = 0; i < 8; i++) {               // B: 2 comps x 128 x 128B
                int f = tid + i*256;
                int comp = f >> 10;
                int rem = f & 1023;
                int n = rem >> 3, j = rem & 7;
                uint32_t dst = sb + SM_B + comp*16384 +
                               SW128((uint32_t)(n*128 + j*16));
                CP_ASYNC16(dst, wsrc + comp*32768 + (nc*128 + n)*64 + j);
            }
            CP_COMMIT();
            CP_WAIT0();
            __syncthreads();
        }

        for (int kc = 0; kc < 8; kc++) {
            const uint32_t cs = (uint32_t)(kc & 1);
            // ---- issue loads for kc+1 into other stage (overlaps with MMA below)
            if (kc < 7) {
                const uint32_t ns = cs ^ 1u;
                const int kn = kc + 1;
#pragma unroll
                for (int i = 0; i < 8; i++) {
                    int f = tid + i*256;
                    int m = f >> 4, jq = f & 15;
                    float4 x = *(const float4*)(enc + (size_t)(m0+m)*HH + kn*64 + jq*4);
                    __half2 h01 = __float22half2_rn(make_float2(x.x, x.y));
                    __half2 h23 = __float22half2_rn(make_float2(x.z, x.w));
                    uint32_t off = SW128((uint32_t)(m*128 + jq*8));
                    *(uint2*)(smem + SM_A + ns*16384 + off) =
                        make_uint2(*(uint32_t*)&h01, *(uint32_t*)&h23);
                }
#pragma unroll
                for (int i = 0; i < 8; i++) {
                    int f = tid + i*256;
                    int comp = f >> 10;
                    int rem = f & 1023;
                    int n = rem >> 3, j = rem & 7;
                    uint32_t dst = sb + SM_B + ns*32768 + comp*16384 +
                                   SW128((uint32_t)(n*128 + j*16));
                    CP_ASYNC16(dst, wsrc + comp*32768 + (nc*128 + n)*64 + kn*8 + j);
                }
                CP_COMMIT();
            }

            // ---- MMAs on current stage
            const uint32_t aBase = sb + SM_A + cs*16384u;
            const uint32_t bBase = sb + SM_B + cs*32768u;
#pragma unroll
            for (int ks = 0; ks < 4; ks++) {
                uint32_t a[4][4];
#pragma unroll
                for (int mf = 0; mf < 4; mf++) {
                    uint32_t ad = aBase +
                        SW128(aRow + (uint32_t)mf*2048u + (uint32_t)ks*32u + aCol);
                    LDSM4(a[mf][0], a[mf][1], a[mf][2], a[mf][3], ad);
                }
                // product 1: Ah * Bh
                {
                    uint32_t bfr[4][2];
#pragma unroll
                    for (int n2 = 0; n2 < 2; n2++) {
                        uint32_t bd = bBase +
                            SW128(bRow + (uint32_t)n2*2048u + (uint32_t)ks*32u + bCol);
                        uint32_t r0, r1, r2, r3;
                        LDSM4(r0, r1, r2, r3, bd);
                        bfr[n2*2][0] = r0;   bfr[n2*2][1] = r1;
                        bfr[n2*2+1][0] = r2; bfr[n2*2+1][1] = r3;
                    }
#pragma unroll
                    for (int mf = 0; mf < 4; mf++)
#pragma unroll
                        for (int nf = 0; nf < 4; nf++)
                            mma16816(c[mf][nf], a[mf], bfr[nf][0], bfr[nf][1]);
                }
                // product 2: Ah * Bl
                {
                    uint32_t bfr[4][2];
#pragma unroll
                    for (int n2 = 0; n2 < 2; n2++) {
                        uint32_t bd = bBase + 16384u +
                            SW128(bRow + (uint32_t)n2*2048u + (uint32_t)ks*32u + bCol);
                        uint32_t r0, r1, r2, r3;
                        LDSM4(r0, r1, r2, r3, bd);
                        bfr[n2*2][0] = r0;   bfr[n2*2][1] = r1;
                        bfr[n2*2+1][0] = r2; bfr[n2*2+1][1] = r3;
                    }
#pragma unroll
                    for (int mf = 0; mf < 4; mf++)
#pragma unroll
                        for (int nf = 0; nf < 4; nf++)
                            mma16816(c[mf][nf], a[mf], bfr[nf][0], bfr[nf][1]);
                }
            }

            CP_WAIT0();        // loads for kc+1 done (overlapped with MMAs above)
            __syncthreads();   // all warps: reads of cs done, writes of ns visible
        }

        // ---- epilogue for this 128-channel chunk
#pragma unroll
        for (int mf = 0; mf < 4; mf++)
#pragma unroll
            for (int nf = 0; nf < 4; nf++) {
                int nb = wn*32 + nf*8 + (lane & 3)*2;
                float q0 = qs[nb],   v0 = vs[nb];
                float q1 = qs[nb+1], v1 = vs[nb+1];
                rowsc[mf*2]   += fast_tanh(c[mf][nf][0] + q0)*v0
                               + fast_tanh(c[mf][nf][1] + q1)*v1;
                rowsc[mf*2+1] += fast_tanh(c[mf][nf][2] + q0)*v0
                               + fast_tanh(c[mf][nf][3] + q1)*v1;
            }
        __syncthreads();   // before qs/vs overwritten next nc
    }

    // reduce over the 4 lanes sharing each row
#pragma unroll
    for (int i = 0; i < 8; i++) {
        rowsc[i] += __shfl_xor_sync(~0u, rowsc[i], 1);
        rowsc[i] += __shfl_xor_sync(~0u, rowsc[i], 2);
    }
    if ((lane & 3) == 0) {
        int r = lane >> 2;
#pragma unroll
        for (int mf = 0; mf < 4; mf++) {
            part[wn*128 + wm*64 + mf*16 + r]     = rowsc[mf*2];
            part[wn*128 + wm*64 + mf*16 + r + 8] = rowsc[mf*2+1];
        }
    }
    __syncthreads();
    if (tid < 128)
        g_scores[m0 + tid] = part[tid] + part[128+tid] + part[256+tid] + part[384+tid];
}

// ---------------------------------------------------------------------------
// softmax over S per batch
// ---------------------------------------------------------------------------
__global__ void softmax_kernel(float* __restrict__ alpha) {
    const int b = blockIdx.x;
    const int tid = threadIdx.x;    // 1024
    const float* sc = g_scores + b*SS;
    __shared__ float red[32];

    float m = -1e30f;
    for (int s = tid; s < SS; s += 1024) m = fmaxf(m, sc[s]);
#pragma unroll
    for (int off = 16; off; off >>= 1) m = fmaxf(m, __shfl_xor_sync(~0u, m, off));
    if ((tid & 31) == 0) red[tid >> 5] = m;
    __syncthreads();
    if (tid < 32) {
        float x = red[tid];
#pragma unroll
        for (int off = 16; off; off >>= 1) x = fmaxf(x, __shfl_xor_sync(~0u, x, off));
        if (tid == 0) red[0] = x;
    }
    __syncthreads();
    m = red[0];
    __syncthreads();

    float sum = 0.f;
    for (int s = tid; s < SS; s += 1024) sum += expf(sc[s] - m);
#pragma unroll
    for (int off = 16; off; off >>= 1) sum += __shfl_xor_sync(~0u, sum, off);
    if ((tid & 31) == 0) red[tid >> 5] = sum;
    __syncthreads();
    if (tid < 32) {
        float x = red[tid];
#pragma unroll
        for (int off = 16; off; off >>= 1) x += __shfl_xor_sync(~0u, x, off);
        if (tid == 0) red[0] = x;
    }
    __syncthreads();
    const float inv = 1.f / red[0];
    for (int s = tid; s < SS; s += 1024)
        alpha[b*SS + s] = expf(sc[s] - m) * inv;
}

// ---------------------------------------------------------------------------
// context: partials over 64 s-chunks of 128 rows, then reduce
// ---------------------------------------------------------------------------
__global__ void ctx_part_kernel(const float* __restrict__ enc,
                                const float* __restrict__ alpha) {
    const int b = blockIdx.x, sc = blockIdx.y;   // 16 x 64
    const int t = threadIdx.x;                    // 128
    __shared__ float al[128];
    al[t] = alpha[b*SS + sc*128 + t];
    __syncthreads();

    const float4* e = (const float4*)(enc + (size_t)b*SS*HH + (size_t)sc*128*HH) + t;
    float4 acc = make_float4(0.f, 0.f, 0.f, 0.f);
#pragma unroll 4
    for (int s = 0; s < 128; s++) {
        float a = al[s];
        float4 vv = e[(size_t)s*128];
        acc.x += a*vv.x; acc.y += a*vv.y; acc.z += a*vv.z; acc.w += a*vv.w;
    }
    ((float4*)(g_ctx_part + (size_t)(b*64 + sc)*HH))[t] = acc;
}

__global__ void ctx_reduce_kernel(float* __restrict__ ctx) {
    const int b = blockIdx.x, h = threadIdx.x;
    float s = 0.f;
#pragma unroll
    for (int i = 0; i < 64; i++)
        s += g_ctx_part[(size_t)(b*64 + i)*HH + h];
    ctx[b*HH + h] = s;
}

// ---------------------------------------------------------------------------
extern "C" void kernel_launch(void* const* d_in, const int* in_sizes, int n_in,
                              void* d_out, int out_size) {
    const float* enc   = (const float*)d_in[0];
    const float* query = (const float*)d_in[1];
    const float* Wh    = (const float*)d_in[2];
    const float* Wq    = (const float*)d_in[3];
    const float* v     = (const float*)d_in[4];

    float* ctx   = (float*)d_out;
    float* alpha = (float*)d_out + BB*HH;

    cudaFuncSetAttribute(scores_mma_kernel,
                         cudaFuncAttributeMaxDynamicSharedMemorySize, SM_TOTAL);

    whsplit_kernel<<<HH*HH/1024, 256>>>(Wh);
    qproj_kernel<<<BB, HH>>>(query, Wq);
    scores_mma_kernel<<<NROWS/128, 256, SM_TOTAL>>>(enc, v);
    softmax_kernel<<<BB, 1024>>>(alpha);
    ctx_part_kernel<<<dim3(BB, 64), 128>>>(enc, alpha);
    ctx_reduce_kernel<<<BB, HH>>>(ctx);
}

// round 6
// speedup vs baseline: 3.7490x; 1.8912x over previous
#include <cuda_runtime.h>
#include <cuda_fp16.h>
#include <math.h>
#include <stdint.h>

#define BB 16
#define SS 8192
#define HH 512
#define NROWS (BB*SS)

// ---------------------------------------------------------------------------
// helpers
// ---------------------------------------------------------------------------
__device__ __forceinline__ uint32_t smem_u32(const void* p) {
    uint32_t a;
    asm("{ .reg .u64 t; cvta.to.shared.u64 t, %1; cvt.u32.u64 %0, t; }" : "=r"(a) : "l"(p));
    return a;
}
#define SW128(o) ((o) ^ (((o) >> 3) & 0x70))

#define LDSM4(r0,r1,r2,r3,addr)                                               \
    asm volatile("ldmatrix.sync.aligned.m8n8.x4.shared.b16 {%0,%1,%2,%3}, [%4];" \
        : "=r"(r0),"=r"(r1),"=r"(r2),"=r"(r3) : "r"(addr))

#define CP_ASYNC16(dst, src)                                                  \
    asm volatile("cp.async.ca.shared.global [%0], [%1], 16;" :: "r"(dst), "l"(src) : "memory")
#define CP_COMMIT()  asm volatile("cp.async.commit_group;" ::: "memory")
#define CP_WAIT0()   asm volatile("cp.async.wait_group 0;" ::: "memory")

__device__ __forceinline__ void mma16816(float* c, const uint32_t* a,
                                         uint32_t b0, uint32_t b1) {
    asm volatile(
        "mma.sync.aligned.m16n8k16.row.col.f32.f16.f16.f32 "
        "{%0,%1,%2,%3}, {%4,%5,%6,%7}, {%8,%9}, {%0,%1,%2,%3};"
        : "+f"(c[0]), "+f"(c[1]), "+f"(c[2]), "+f"(c[3])
        : "r"(a[0]), "r"(a[1]), "r"(a[2]), "r"(a[3]), "r"(b0), "r"(b1));
}

__device__ __forceinline__ float fast_tanh(float x) {
    float xc = fminf(x, 30.f);
    float e  = __expf(2.f * xc);
    return __fdividef(e - 1.f, e + 1.f);
}

// ---------------------------------------------------------------------------
// scratch
// ---------------------------------------------------------------------------
__device__ float g_qproj[BB*HH];
__device__ float g_scores[BB*SS];
__device__ float g_ctx_part[BB*64*HH];
__device__ __align__(16) __half g_Wh16[HH*HH];   // W_h cast to fp16, [o][k]

// smem layout (bytes): 2-stage double buffer
#define SM_A     0                      // 2 stages x 128 rows x 128B = 32KB
#define SM_B     32768                  // 2 stages x 128 rows x 128B = 32KB
#define SM_Q     65536                  // 128 floats
#define SM_V     66048                  // 128 floats
#define SM_PART  66560                  // 4 x 128 floats
#define SM_TOTAL 68608

// ---------------------------------------------------------------------------
// cast W_h to fp16
// ---------------------------------------------------------------------------
__global__ void whcast_kernel(const float* __restrict__ Wh) {
    int i0 = (blockIdx.x * 256 + threadIdx.x) * 4;
    float4 x = *(const float4*)(Wh + i0);
    __half2 h01 = __float22half2_rn(make_float2(x.x, x.y));
    __half2 h23 = __float22half2_rn(make_float2(x.z, x.w));
    *(uint2*)(g_Wh16 + i0) = make_uint2(*(uint32_t*)&h01, *(uint32_t*)&h23);
}

// ---------------------------------------------------------------------------
// q_proj[b][o] = query[b,:] . W_q[o,:]   (fp32, exact)
// ---------------------------------------------------------------------------
__global__ void qproj_kernel(const float* __restrict__ query,
                             const float* __restrict__ Wq) {
    int b = blockIdx.x, o = threadIdx.x;
    __shared__ float q[HH];
    q[o] = query[b*HH + o];
    __syncthreads();
    const float* w = Wq + (size_t)o*HH;
    float acc = 0.f;
#pragma unroll 8
    for (int k = 0; k < HH; k++) acc += q[k] * w[k];
    g_qproj[b*HH + o] = acc;
}

// ---------------------------------------------------------------------------
// scores via single-pass fp16 mma:  D = fp16(enc) x fp16(W_h)^T  (fp32 accum)
// CTA: 128 rows x full H. 8 warps = 2(m) x 4(n), warp tile 64x32.
// nc: 4 chunks of 128 output channels; kc: 8 chunks of 64 k, double-buffered.
// ---------------------------------------------------------------------------
__global__ __launch_bounds__(256, 2)
void scores_mma_kernel(const float* __restrict__ enc,
                       const float* __restrict__ v) {
    extern __shared__ char smem[];
    const uint32_t sb = smem_u32(smem);
    const int tid  = threadIdx.x;
    const int lane = tid & 31;
    const int wid  = tid >> 5;
    const int wm   = wid & 1;          // 0..1  (64 rows each)
    const int wn   = wid >> 1;         // 0..3  (32 cols each)
    const int m0   = blockIdx.x * 128;
    const int b    = m0 / SS;

    float* qs   = (float*)(smem + SM_Q);
    float* vs   = (float*)(smem + SM_V);
    float* part = (float*)(smem + SM_PART);   // [4][128]

    // per-thread ldmatrix base offsets (within a 128-row x 128B tile)
    const uint32_t aRow = (uint32_t)(wm*64 + (lane & 15)) * 128u;
    const uint32_t aCol = ((lane >> 4) & 1) * 16u;
    const uint32_t bRow = (uint32_t)(wn*32 + (lane & 7) + ((lane & 16) ? 8 : 0)) * 128u;
    const uint32_t bCol = ((lane & 8) ? 16u : 0u);

    const uint4* wsrc = (const uint4*)g_Wh16;   // 64 uint4 per o-row

    float rowsc[8];
#pragma unroll
    for (int i = 0; i < 8; i++) rowsc[i] = 0.f;

    for (int nc = 0; nc < 4; nc++) {
        if (tid < 128) {
            qs[tid] = g_qproj[b*HH + nc*128 + tid];
            vs[tid] = v[nc*128 + tid];
        }

        float c[4][4][4];
#pragma unroll
        for (int mf = 0; mf < 4; mf++)
#pragma unroll
            for (int nf = 0; nf < 4; nf++)
#pragma unroll
                for (int e = 0; e < 4; e++) c[mf][nf][e] = 0.f;

        // ---- prologue: load kc=0 into stage 0
        {
#pragma unroll
            for (int i = 0; i < 8; i++) {               // A: 128x64 fp32 -> fp16
                int f = tid + i*256;
                int m = f >> 4, jq = f & 15;
                float4 x = *(const float4*)(enc + (size_t)(m0+m)*HH + jq*4);
                __half2 h01 = __float22half2_rn(make_float2(x.x, x.y));
                __half2 h23 = __float22half2_rn(make_float2(x.z, x.w));
                uint32_t off = SW128((uint32_t)(m*128 + jq*8));
                *(uint2*)(smem + SM_A + off) =
                    make_uint2(*(uint32_t*)&h01, *(uint32_t*)&h23);
            }
#pragma unroll
            for (int i = 0; i < 4; i++) {               // B: 128 rows x 128B
                int f = tid + i*256;
                int n = f >> 3, j = f & 7;
                uint32_t dst = sb + SM_B + SW128((uint32_t)(n*128 + j*16));
                CP_ASYNC16(dst, wsrc + (nc*128 + n)*64 + j);
            }
            CP_COMMIT();
            CP_WAIT0();
            __syncthreads();
        }

        for (int kc = 0; kc < 8; kc++) {
            const uint32_t cs = (uint32_t)(kc & 1);
            // ---- issue loads for kc+1 into other stage (overlaps with MMA below)
            if (kc < 7) {
                const uint32_t ns = cs ^ 1u;
                const int kn = kc + 1;
#pragma unroll
                for (int i = 0; i < 8; i++) {
                    int f = tid + i*256;
                    int m = f >> 4, jq = f & 15;
                    float4 x = *(const float4*)(enc + (size_t)(m0+m)*HH + kn*64 + jq*4);
                    __half2 h01 = __float22half2_rn(make_float2(x.x, x.y));
                    __half2 h23 = __float22half2_rn(make_float2(x.z, x.w));
                    uint32_t off = SW128((uint32_t)(m*128 + jq*8));
                    *(uint2*)(smem + SM_A + ns*16384 + off) =
                        make_uint2(*(uint32_t*)&h01, *(uint32_t*)&h23);
                }
#pragma unroll
                for (int i = 0; i < 4; i++) {
                    int f = tid + i*256;
                    int n = f >> 3, j = f & 7;
                    uint32_t dst = sb + SM_B + ns*16384u +
                                   SW128((uint32_t)(n*128 + j*16));
                    CP_ASYNC16(dst, wsrc + (nc*128 + n)*64 + kn*8 + j);
                }
                CP_COMMIT();
            }

            // ---- MMAs on current stage
            const uint32_t aBase = sb + SM_A + cs*16384u;
            const uint32_t bBase = sb + SM_B + cs*16384u;
#pragma unroll
            for (int ks = 0; ks < 4; ks++) {
                uint32_t a[4][4];
#pragma unroll
                for (int mf = 0; mf < 4; mf++) {
                    uint32_t ad = aBase +
                        SW128(aRow + (uint32_t)mf*2048u + (uint32_t)ks*32u + aCol);
                    LDSM4(a[mf][0], a[mf][1], a[mf][2], a[mf][3], ad);
                }
                uint32_t bfr[4][2];
#pragma unroll
                for (int n2 = 0; n2 < 2; n2++) {
                    uint32_t bd = bBase +
                        SW128(bRow + (uint32_t)n2*2048u + (uint32_t)ks*32u + bCol);
                    uint32_t r0, r1, r2, r3;
                    LDSM4(r0, r1, r2, r3, bd);
                    bfr[n2*2][0] = r0;   bfr[n2*2][1] = r1;
                    bfr[n2*2+1][0] = r2; bfr[n2*2+1][1] = r3;
                }
#pragma unroll
                for (int mf = 0; mf < 4; mf++)
#pragma unroll
                    for (int nf = 0; nf < 4; nf++)
                        mma16816(c[mf][nf], a[mf], bfr[nf][0], bfr[nf][1]);
            }

            CP_WAIT0();        // loads for kc+1 landed (overlapped with MMAs)
            __syncthreads();   // all warps done reading cs; ns writes visible
        }

        // ---- epilogue for this 128-channel chunk
#pragma unroll
        for (int mf = 0; mf < 4; mf++)
#pragma unroll
            for (int nf = 0; nf < 4; nf++) {
                int nb = wn*32 + nf*8 + (lane & 3)*2;
                float q0 = qs[nb],   v0 = vs[nb];
                float q1 = qs[nb+1], v1 = vs[nb+1];
                rowsc[mf*2]   += fast_tanh(c[mf][nf][0] + q0)*v0
                               + fast_tanh(c[mf][nf][1] + q1)*v1;
                rowsc[mf*2+1] += fast_tanh(c[mf][nf][2] + q0)*v0
                               + fast_tanh(c[mf][nf][3] + q1)*v1;
            }
        __syncthreads();   // before qs/vs overwritten next nc
    }

    // reduce over the 4 lanes sharing each row
#pragma unroll
    for (int i = 0; i < 8; i++) {
        rowsc[i] += __shfl_xor_sync(~0u, rowsc[i], 1);
        rowsc[i] += __shfl_xor_sync(~0u, rowsc[i], 2);
    }
    if ((lane & 3) == 0) {
        int r = lane >> 2;
#pragma unroll
        for (int mf = 0; mf < 4; mf++) {
            part[wn*128 + wm*64 + mf*16 + r]     = rowsc[mf*2];
            part[wn*128 + wm*64 + mf*16 + r + 8] = rowsc[mf*2+1];
        }
    }
    __syncthreads();
    if (tid < 128)
        g_scores[m0 + tid] = part[tid] + part[128+tid] + part[256+tid] + part[384+tid];
}

// ---------------------------------------------------------------------------
// softmax over S per batch
// ---------------------------------------------------------------------------
__global__ void softmax_kernel(float* __restrict__ alpha) {
    const int b = blockIdx.x;
    const int tid = threadIdx.x;    // 1024
    const float* sc = g_scores + b*SS;
    __shared__ float red[32];

    float m = -1e30f;
    for (int s = tid; s < SS; s += 1024) m = fmaxf(m, sc[s]);
#pragma unroll
    for (int off = 16; off; off >>= 1) m = fmaxf(m, __shfl_xor_sync(~0u, m, off));
    if ((tid & 31) == 0) red[tid >> 5] = m;
    __syncthreads();
    if (tid < 32) {
        float x = red[tid];
#pragma unroll
        for (int off = 16; off; off >>= 1) x = fmaxf(x, __shfl_xor_sync(~0u, x, off));
        if (tid == 0) red[0] = x;
    }
    __syncthreads();
    m = red[0];
    __syncthreads();

    float sum = 0.f;
    for (int s = tid; s < SS; s += 1024) sum += expf(sc[s] - m);
#pragma unroll
    for (int off = 16; off; off >>= 1) sum += __shfl_xor_sync(~0u, sum, off);
    if ((tid & 31) == 0) red[tid >> 5] = sum;
    __syncthreads();
    if (tid < 32) {
        float x = red[tid];
#pragma unroll
        for (int off = 16; off; off >>= 1) x += __shfl_xor_sync(~0u, x, off);
        if (tid == 0) red[0] = x;
    }
    __syncthreads();
    const float inv = 1.f / red[0];
    for (int s = tid; s < SS; s += 1024)
        alpha[b*SS + s] = expf(sc[s] - m) * inv;
}

// ---------------------------------------------------------------------------
// context: partials over 64 s-chunks of 128 rows, then reduce
// ---------------------------------------------------------------------------
__global__ void ctx_part_kernel(const float* __restrict__ enc,
                                const float* __restrict__ alpha) {
    const int b = blockIdx.x, sc = blockIdx.y;   // 16 x 64
    const int t = threadIdx.x;                    // 128
    __shared__ float al[128];
    al[t] = alpha[b*SS + sc*128 + t];
    __syncthreads();

    const float4* e = (const float4*)(enc + (size_t)b*SS*HH + (size_t)sc*128*HH) + t;
    float4 acc = make_float4(0.f, 0.f, 0.f, 0.f);
#pragma unroll 8
    for (int s = 0; s < 128; s++) {
        float a = al[s];
        float4 vv = e[(size_t)s*128];
        acc.x += a*vv.x; acc.y += a*vv.y; acc.z += a*vv.z; acc.w += a*vv.w;
    }
    ((float4*)(g_ctx_part + (size_t)(b*64 + sc)*HH))[t] = acc;
}

__global__ void ctx_reduce_kernel(float* __restrict__ ctx) {
    const int b = blockIdx.x, h = threadIdx.x;
    float s = 0.f;
#pragma unroll
    for (int i = 0; i < 64; i++)
        s += g_ctx_part[(size_t)(b*64 + i)*HH + h];
    ctx[b*HH + h] = s;
}

// ---------------------------------------------------------------------------
extern "C" void kernel_launch(void* const* d_in, const int* in_sizes, int n_in,
                              void* d_out, int out_size) {
    const float* enc   = (const float*)d_in[0];
    const float* query = (const float*)d_in[1];
    const float* Wh    = (const float*)d_in[2];
    const float* Wq    = (const float*)d_in[3];
    const float* v     = (const float*)d_in[4];

    float* ctx   = (float*)d_out;
    float* alpha = (float*)d_out + BB*HH;

    cudaFuncSetAttribute(scores_mma_kernel,
                         cudaFuncAttributeMaxDynamicSharedMemorySize, SM_TOTAL);

    whcast_kernel<<<HH*HH/1024, 256>>>(Wh);
    qproj_kernel<<<BB, HH>>>(query, Wq);
    scores_mma_kernel<<<NROWS/128, 256, SM_TOTAL>>>(enc, v);
    softmax_kernel<<<BB, 1024>>>(alpha);
    ctx_part_kernel<<<dim3(BB, 64), 128>>>(enc, alpha);
    ctx_reduce_kernel<<<BB, HH>>>(ctx);
}